// round 13
// baseline (speedup 1.0000x reference)
#include <cuda_runtime.h>
#include <cuda_bf16.h>
#include <cstdint>

// Problem shape (fixed by dataset): N=2,000,000 atoms, D=64, HID=32, H=3, G=50,000
#define D_DIM   64
#define HID_DIM 32
#define H_DIM   3

#define MAX_N 2000000
#define MAX_G 50000
#define SEG_CAP 128

typedef unsigned long long ull;

// Scratch (device globals)
__device__ float g_scores[(size_t)MAX_N * H_DIM];   // big-segment fallback only
__device__ int   g_segstart[MAX_G + 1];

// ---------------- packed fp32x2 helpers ----------------
__device__ __forceinline__ ull pack2(float v) {
    ull r; asm("mov.b64 %0, {%1, %1};" : "=l"(r) : "f"(v)); return r;
}
__device__ __forceinline__ ull fma2(ull a, ull b, ull c) {
    ull d; asm("fma.rn.f32x2 %0, %1, %2, %3;" : "=l"(d) : "l"(a), "l"(b), "l"(c)); return d;
}
__device__ __forceinline__ void unpack2(ull v, float& lo, float& hi) {
    asm("mov.b64 {%0, %1}, %2;" : "=f"(lo), "=f"(hi) : "l"(v));
}

// ---------------- bf16 helpers ----------------
__device__ __forceinline__ uint32_t pk2bf(float a, float b) {
    __nv_bfloat162 h = __floats2bfloat162_rn(a, b);
    return *reinterpret_cast<uint32_t*>(&h);
}
__device__ __forceinline__ float bfhi(float x) {
    return __bfloat162float(__float2bfloat16_rn(x));
}
// hi-part via truncation: one PRMT packs the top 16 bits of (a,b) -> bf16x2
__device__ __forceinline__ uint32_t pkhi_trunc(float a, float b) {
    uint32_t r;
    asm("prmt.b32 %0, %1, %2, 0x7632;"
        : "=r"(r) : "r"(__float_as_uint(a)), "r"(__float_as_uint(b)));
    return r;
}
__device__ __forceinline__ float trunchi(float x) {
    return __uint_as_float(__float_as_uint(x) & 0xffff0000u);
}

// warp-level tensor-core MMA (sm_80+ feature set; compiles for plain sm_103)
__device__ __forceinline__ void mma16816(float c[4],
    uint32_t a0, uint32_t a1, uint32_t a2, uint32_t a3,
    uint32_t b0, uint32_t b1)
{
    asm volatile(
        "mma.sync.aligned.m16n8k16.row.col.f32.bf16.bf16.f32 "
        "{%0,%1,%2,%3}, {%4,%5,%6,%7}, {%8,%9}, {%0,%1,%2,%3};"
        : "+f"(c[0]), "+f"(c[1]), "+f"(c[2]), "+f"(c[3])
        : "r"(a0), "r"(a1), "r"(a2), "r"(a3), "r"(b0), "r"(b1));
}

// ---------------------------------------------------------------------------
// Kernel 1: segment boundaries from sorted owner array.
// ---------------------------------------------------------------------------
__global__ void k_bounds(const int* __restrict__ owner, int N, int G)
{
    int i = blockIdx.x * blockDim.x + threadIdx.x;
    if (i >= N) return;
    int o = owner[i];
    if (i == 0) {
        for (int g = 0; g <= o; ++g) g_segstart[g] = 0;
    } else {
        int po = owner[i - 1];
        for (int g = po + 1; g <= o; ++g) g_segstart[g] = i;
    }
    if (i == N - 1) {
        for (int g = o + 1; g <= G; ++g) g_segstart[g] = N;
    }
}

// ---------------------------------------------------------------------------
// Kernel 2 (FUSED): warp per segment; weights in registers (SHFL broadcast);
// score staging via float4 (1 STS.128 / 1 LDS.128 per atom);
// Phase C: 4 atoms per iteration (2 independent LDG.128 per lane).
// ---------------------------------------------------------------------------
__global__ __launch_bounds__(128, 6) void k_fused(
    const float* __restrict__ X,
    const float* __restrict__ w1, const float* __restrict__ b1,
    const float* __restrict__ w2, const float* __restrict__ b2,
    float* __restrict__ out, int N, int G)
{
    __shared__ uint4  sB[4][4][32];          // 8 KB  {bh0,bh1,bl0,bl1}
    __shared__ uint4  sE[4][2][32];          // 4 KB  {b1, w2_0, w2_1, w2_2}
    __shared__ float4 swbuf[4][SEG_CAP];     // 8 KB  packed scores {s0,s1,s2,pad}

    const int lane = threadIdx.x & 31;
    const int wid  = threadIdx.x >> 5;
    const int g    = lane >> 2;   // row group 0..7
    const int tig  = lane & 3;    // thread-in-group
    const int half = lane >> 4;   // 0 or 1 (phase-C row select)
    const int dq   = (lane & 15) * 4;   // phase-C d-column base

    if (wid == 0) {
#pragma unroll
        for (int t = 0; t < 4; ++t) {
            const int col = g + 8 * t;
#pragma unroll
            for (int s = 0; s < 4; ++s) {
                const int p0 = 16 * s + 4 * tig;   // sigma k-permutation
                float w00 = __ldg(&w1[(p0 + 0) * HID_DIM + col]);
                float w01 = __ldg(&w1[(p0 + 1) * HID_DIM + col]);
                float w08 = __ldg(&w1[(p0 + 2) * HID_DIM + col]);
                float w09 = __ldg(&w1[(p0 + 3) * HID_DIM + col]);
                uint4 v;
                v.x = pk2bf(w00, w01);
                v.y = pk2bf(w08, w09);
                v.z = pk2bf(w00 - bfhi(w00), w01 - bfhi(w01));
                v.w = pk2bf(w08 - bfhi(w08), w09 - bfhi(w09));
                sB[t][s][lane] = v;
            }
#pragma unroll
            for (int e = 0; e < 2; ++e) {
                const int col2 = 8 * t + tig * 2 + e;
                uint4 v;
                v.x = __float_as_uint(__ldg(&b1[col2]));
                v.y = __float_as_uint(__ldg(&w2[col2 * H_DIM + 0]));
                v.z = __float_as_uint(__ldg(&w2[col2 * H_DIM + 1]));
                v.w = __float_as_uint(__ldg(&w2[col2 * H_DIM + 2]));
                sE[t][e][lane] = v;
            }
        }
    }
    __syncthreads();

    const float bb0 = __ldg(&b2[0]), bb1 = __ldg(&b2[1]), bb2 = __ldg(&b2[2]);

    float4* swp = swbuf[wid];

    const int warp0 = blockIdx.x * 4 + wid;
    const int nwarp = gridDim.x * 4;

    for (int seg = warp0; seg < G; seg += nwarp) {
        const int s0  = g_segstart[seg];
        const int s1  = g_segstart[seg + 1];
        const int cnt = s1 - s0;
        float* outg = out + (size_t)seg * (D_DIM * H_DIM);

        if (cnt <= 0) {
            if (lane < 16) {
                float4 z = make_float4(0.f, 0.f, 0.f, 0.f);
                float4* o4 = reinterpret_cast<float4*>(outg + lane * 12);
                o4[0] = z; o4[1] = z; o4[2] = z;
            }
            continue;
        }

        // =========== Phase A: scores (mma.sync, k-permuted, trunc split) =====
        const bool fast = (cnt <= SEG_CAP);
        const int ntile = (cnt + 15) >> 4;
        for (int ti = 0; ti < ntile; ++ti) {
            float acc[4][4];
#pragma unroll
            for (int t = 0; t < 4; ++t) {
                acc[t][0] = 0.f; acc[t][1] = 0.f; acc[t][2] = 0.f; acc[t][3] = 0.f;
            }
            const int r0 = s0 + ti * 16 + g;
            const int r1 = r0 + 8;
            const float* x0 = X + (size_t)(r0 < s1 ? r0 : s1 - 1) * D_DIM;
            const float* x1 = X + (size_t)(r1 < s1 ? r1 : s1 - 1) * D_DIM;

#pragma unroll
            for (int s = 0; s < 4; ++s) {
                const int ks = 16 * s + 4 * tig;
                float4 u0 = *reinterpret_cast<const float4*>(x0 + ks);
                float4 u1 = *reinterpret_cast<const float4*>(x1 + ks);

                uint32_t ah0 = pkhi_trunc(u0.x, u0.y);
                uint32_t ah1 = pkhi_trunc(u1.x, u1.y);
                uint32_t ah2 = pkhi_trunc(u0.z, u0.w);
                uint32_t ah3 = pkhi_trunc(u1.z, u1.w);
                uint32_t al0 = pk2bf(u0.x - trunchi(u0.x), u0.y - trunchi(u0.y));
                uint32_t al1 = pk2bf(u1.x - trunchi(u1.x), u1.y - trunchi(u1.y));
                uint32_t al2 = pk2bf(u0.z - trunchi(u0.z), u0.w - trunchi(u0.w));
                uint32_t al3 = pk2bf(u1.z - trunchi(u1.z), u1.w - trunchi(u1.w));

#pragma unroll
                for (int t = 0; t < 4; ++t) {
                    uint4 bf = sB[t][s][lane];
                    mma16816(acc[t], ah0, ah1, ah2, ah3, bf.x, bf.y);
                    mma16816(acc[t], ah0, ah1, ah2, ah3, bf.z, bf.w);
                    mma16816(acc[t], al0, al1, al2, al3, bf.x, bf.y);
                }
            }

#pragma unroll
            for (int row = 0; row < 2; ++row) {
                float q0 = 0.f, q1 = 0.f, q2 = 0.f;
#pragma unroll
                for (int t = 0; t < 4; ++t) {
#pragma unroll
                    for (int e = 0; e < 2; ++e) {
                        uint4 c = sE[t][e][lane];
                        float h = acc[t][row * 2 + e] + __uint_as_float(c.x);
                        float act = __fdividef(h, 1.0f + __expf(-h));
                        q0 = fmaf(act, __uint_as_float(c.y), q0);
                        q1 = fmaf(act, __uint_as_float(c.z), q1);
                        q2 = fmaf(act, __uint_as_float(c.w), q2);
                    }
                }
                q0 += __shfl_xor_sync(0xffffffffu, q0, 1);
                q0 += __shfl_xor_sync(0xffffffffu, q0, 2);
                q1 += __shfl_xor_sync(0xffffffffu, q1, 1);
                q1 += __shfl_xor_sync(0xffffffffu, q1, 2);
                q2 += __shfl_xor_sync(0xffffffffu, q2, 1);
                q2 += __shfl_xor_sync(0xffffffffu, q2, 2);

                const int idx = ti * 16 + g + 8 * row;
                if (tig == 0 && idx < cnt) {
                    if (fast) {
                        swp[idx] = make_float4(q0 + bb0, q1 + bb1, q2 + bb2, 0.f);
                    } else {
                        size_t o = (size_t)(s0 + idx) * H_DIM;
                        g_scores[o + 0] = q0 + bb0;
                        g_scores[o + 1] = q1 + bb1;
                        g_scores[o + 2] = q2 + bb2;
                    }
                }
            }
        }
        __syncwarp();

        // ---- phase-C accumulators: lane owns d = dq..dq+3 for its half-rows
        ull a00 = 0, a01 = 0, a10 = 0, a11 = 0, a20 = 0, a21 = 0;

        // phase C over a chunk of <=128 atoms with weights in exv regs
        auto phase_c = [&](int gbase, int clen, const float (&exv)[4][3]) {
#pragma unroll
            for (int q = 0; q < 4; ++q) {
                const int blk = 32 * q;
                if (blk >= clen) break;
                const int lim = (clen - blk < 32) ? (clen - blk) : 32;
                const float ws0 = exv[q][0], ws1 = exv[q][1], ws2 = exv[q][2];
                const float* Xb = X + (size_t)(gbase + blk) * D_DIM + dq;
                int aa = 0;
                // main: 4 atoms (2 independent pairs) per iteration
                for (; aa + 4 <= lim; aa += 4) {
                    const int i0 = aa + half;
                    const int i1 = aa + 2 + half;
                    float wa0 = __shfl_sync(0xffffffffu, ws0, i0);
                    float wa1 = __shfl_sync(0xffffffffu, ws1, i0);
                    float wa2 = __shfl_sync(0xffffffffu, ws2, i0);
                    float wb0 = __shfl_sync(0xffffffffu, ws0, i1);
                    float wb1 = __shfl_sync(0xffffffffu, ws1, i1);
                    float wb2 = __shfl_sync(0xffffffffu, ws2, i1);
                    const float4 xa = *reinterpret_cast<const float4*>(
                        Xb + (size_t)i0 * D_DIM);
                    const float4 xb = *reinterpret_cast<const float4*>(
                        Xb + (size_t)i1 * D_DIM);
                    const ull* pa = reinterpret_cast<const ull*>(&xa);
                    const ull* pb = reinterpret_cast<const ull*>(&xb);
                    ull qa0 = pack2(wa0), qa1 = pack2(wa1), qa2 = pack2(wa2);
                    ull qb0 = pack2(wb0), qb1 = pack2(wb1), qb2 = pack2(wb2);
                    a00 = fma2(pa[0], qa0, a00); a01 = fma2(pa[1], qa0, a01);
                    a10 = fma2(pa[0], qa1, a10); a11 = fma2(pa[1], qa1, a11);
                    a20 = fma2(pa[0], qa2, a20); a21 = fma2(pa[1], qa2, a21);
                    a00 = fma2(pb[0], qb0, a00); a01 = fma2(pb[1], qb0, a01);
                    a10 = fma2(pb[0], qb1, a10); a11 = fma2(pb[1], qb1, a11);
                    a20 = fma2(pb[0], qb2, a20); a21 = fma2(pb[1], qb2, a21);
                }
                // tail: guarded pairs
                for (; aa < lim; aa += 2) {
                    const int idx = aa + half;
                    const int idc = idx < lim ? idx : lim - 1;
                    float w0 = __shfl_sync(0xffffffffu, ws0, idc);
                    float w1v = __shfl_sync(0xffffffffu, ws1, idc);
                    float w2v = __shfl_sync(0xffffffffu, ws2, idc);
                    if (idx >= lim) { w0 = 0.f; w1v = 0.f; w2v = 0.f; }
                    const float4 xv = *reinterpret_cast<const float4*>(
                        Xb + (size_t)idc * D_DIM);
                    const ull* xp = reinterpret_cast<const ull*>(&xv);
                    ull p0 = pack2(w0), p1 = pack2(w1v), p2 = pack2(w2v);
                    a00 = fma2(xp[0], p0, a00); a01 = fma2(xp[1], p0, a01);
                    a10 = fma2(xp[0], p1, a10); a11 = fma2(xp[1], p1, a11);
                    a20 = fma2(xp[0], p2, a20); a21 = fma2(xp[1], p2, a21);
                }
            }
        };

        if (fast) {
            // ---- Phase B: scores -> regs (LDS.128), softmax via shuffles ----
            float exv[4][3];
            float m0 = -3.4e38f, m1 = -3.4e38f, m2 = -3.4e38f;
#pragma unroll
            for (int q = 0; q < 4; ++q) {
                int a = lane + 32 * q;
                if (a < cnt) {
                    float4 sc = swp[a];
                    exv[q][0] = sc.x; exv[q][1] = sc.y; exv[q][2] = sc.z;
                    m0 = fmaxf(m0, sc.x);
                    m1 = fmaxf(m1, sc.y);
                    m2 = fmaxf(m2, sc.z);
                } else {
                    exv[q][0] = -3.4e38f; exv[q][1] = -3.4e38f; exv[q][2] = -3.4e38f;
                }
            }
#pragma unroll
            for (int off = 16; off; off >>= 1) {
                m0 = fmaxf(m0, __shfl_xor_sync(0xffffffffu, m0, off));
                m1 = fmaxf(m1, __shfl_xor_sync(0xffffffffu, m1, off));
                m2 = fmaxf(m2, __shfl_xor_sync(0xffffffffu, m2, off));
            }
            float e0 = 0.f, e1 = 0.f, e2 = 0.f;
#pragma unroll
            for (int q = 0; q < 4; ++q) {
                exv[q][0] = __expf(exv[q][0] - m0); e0 += exv[q][0];
                exv[q][1] = __expf(exv[q][1] - m1); e1 += exv[q][1];
                exv[q][2] = __expf(exv[q][2] - m2); e2 += exv[q][2];
            }
#pragma unroll
            for (int off = 16; off; off >>= 1) {
                e0 += __shfl_xor_sync(0xffffffffu, e0, off);
                e1 += __shfl_xor_sync(0xffffffffu, e1, off);
                e2 += __shfl_xor_sync(0xffffffffu, e2, off);
            }
            const float r0v = 1.0f / e0, r1v = 1.0f / e1, r2v = 1.0f / e2;
#pragma unroll
            for (int q = 0; q < 4; ++q) {
                exv[q][0] *= r0v; exv[q][1] *= r1v; exv[q][2] *= r2v;
            }
            phase_c(s0, cnt, exv);
        } else {
            // ---- big segment: m/r over g_scores, then chunked phase C
            float m0 = -3.4e38f, m1 = -3.4e38f, m2 = -3.4e38f;
            for (int n = s0 + lane; n < s1; n += 32) {
                size_t o = (size_t)n * H_DIM;
                m0 = fmaxf(m0, g_scores[o + 0]);
                m1 = fmaxf(m1, g_scores[o + 1]);
                m2 = fmaxf(m2, g_scores[o + 2]);
            }
#pragma unroll
            for (int off = 16; off; off >>= 1) {
                m0 = fmaxf(m0, __shfl_xor_sync(0xffffffffu, m0, off));
                m1 = fmaxf(m1, __shfl_xor_sync(0xffffffffu, m1, off));
                m2 = fmaxf(m2, __shfl_xor_sync(0xffffffffu, m2, off));
            }
            float e0 = 0.f, e1 = 0.f, e2 = 0.f;
            for (int n = s0 + lane; n < s1; n += 32) {
                size_t o = (size_t)n * H_DIM;
                e0 += __expf(g_scores[o + 0] - m0);
                e1 += __expf(g_scores[o + 1] - m1);
                e2 += __expf(g_scores[o + 2] - m2);
            }
#pragma unroll
            for (int off = 16; off; off >>= 1) {
                e0 += __shfl_xor_sync(0xffffffffu, e0, off);
                e1 += __shfl_xor_sync(0xffffffffu, e1, off);
                e2 += __shfl_xor_sync(0xffffffffu, e2, off);
            }
            const float r0v = 1.0f / e0, r1v = 1.0f / e1, r2v = 1.0f / e2;

            for (int cb = 0; cb < cnt; cb += SEG_CAP) {
                const int clen = min(SEG_CAP, cnt - cb);
                float exv[4][3];
#pragma unroll
                for (int q = 0; q < 4; ++q) {
                    int a = lane + 32 * q;
                    if (a < clen) {
                        size_t o = (size_t)(s0 + cb + a) * H_DIM;
                        exv[q][0] = __expf(g_scores[o + 0] - m0) * r0v;
                        exv[q][1] = __expf(g_scores[o + 1] - m1) * r1v;
                        exv[q][2] = __expf(g_scores[o + 2] - m2) * r2v;
                    } else {
                        exv[q][0] = 0.f; exv[q][1] = 0.f; exv[q][2] = 0.f;
                    }
                }
                phase_c(s0 + cb, clen, exv);
            }
        }

        // ---- merge half-warps and write out: lane<16 owns d = lane*4..+3 ----
        float v[12];
        unpack2(a00, v[0], v[3]);   // d0h0, d1h0
        unpack2(a10, v[1], v[4]);   // d0h1, d1h1
        unpack2(a20, v[2], v[5]);   // d0h2, d1h2
        unpack2(a01, v[6], v[9]);   // d2h0, d3h0
        unpack2(a11, v[7], v[10]);  // d2h1, d3h1
        unpack2(a21, v[8], v[11]);  // d2h2, d3h2
#pragma unroll
        for (int i = 0; i < 12; ++i)
            v[i] += __shfl_xor_sync(0xffffffffu, v[i], 16);
        if (lane < 16) {
            float4* o4 = reinterpret_cast<float4*>(outg + lane * 12);
            o4[0] = make_float4(v[0], v[1], v[2],  v[3]);
            o4[1] = make_float4(v[4], v[5], v[6],  v[7]);
            o4[2] = make_float4(v[8], v[9], v[10], v[11]);
        }
    }
}

// ---------------------------------------------------------------------------
extern "C" void kernel_launch(void* const* d_in, const int* in_sizes, int n_in,
                              void* d_out, int out_size)
{
    const float* X     = (const float*)d_in[0];
    const float* w1    = (const float*)d_in[1];
    const float* b1    = (const float*)d_in[2];
    const float* w2    = (const float*)d_in[3];
    const float* b2    = (const float*)d_in[4];
    const int*   owner = (const int*)  d_in[5];

    const int N = in_sizes[5];
    const int G = out_size / (D_DIM * H_DIM);

    k_bounds<<<(N + 255) / 256, 256>>>(owner, N, G);
    k_fused<<<1036, 128>>>(X, w1, b1, w2, b2, (float*)d_out, N, G);
}

// round 14
// speedup vs baseline: 1.2600x; 1.2600x over previous
#include <cuda_runtime.h>
#include <cuda_bf16.h>
#include <cstdint>

// Problem shape (fixed by dataset): N=2,000,000 atoms, D=64, HID=32, H=3, G=50,000
#define D_DIM   64
#define HID_DIM 32
#define H_DIM   3

#define MAX_N 2000000
#define MAX_G 50000
#define SEG_CAP 128

typedef unsigned long long ull;

// Scratch (device globals)
__device__ float g_scores[(size_t)MAX_N * H_DIM];   // big-segment fallback only
__device__ int   g_segstart[MAX_G + 1];

// ---------------- packed fp32x2 helpers ----------------
__device__ __forceinline__ ull pack2(float v) {
    ull r; asm("mov.b64 %0, {%1, %1};" : "=l"(r) : "f"(v)); return r;
}
__device__ __forceinline__ ull fma2(ull a, ull b, ull c) {
    ull d; asm("fma.rn.f32x2 %0, %1, %2, %3;" : "=l"(d) : "l"(a), "l"(b), "l"(c)); return d;
}
__device__ __forceinline__ void unpack2(ull v, float& lo, float& hi) {
    asm("mov.b64 {%0, %1}, %2;" : "=f"(lo), "=f"(hi) : "l"(v));
}

// ---------------- bf16 helpers ----------------
__device__ __forceinline__ uint32_t pk2bf(float a, float b) {
    __nv_bfloat162 h = __floats2bfloat162_rn(a, b);
    return *reinterpret_cast<uint32_t*>(&h);
}
__device__ __forceinline__ float bfhi(float x) {
    return __bfloat162float(__float2bfloat16_rn(x));
}
// hi-part via truncation: one PRMT packs the top 16 bits of (a,b) -> bf16x2
__device__ __forceinline__ uint32_t pkhi_trunc(float a, float b) {
    uint32_t r;
    asm("prmt.b32 %0, %1, %2, 0x7632;"
        : "=r"(r) : "r"(__float_as_uint(a)), "r"(__float_as_uint(b)));
    return r;
}
__device__ __forceinline__ float trunchi(float x) {
    return __uint_as_float(__float_as_uint(x) & 0xffff0000u);
}

// warp-level tensor-core MMA (sm_80+ feature set; compiles for plain sm_103)
__device__ __forceinline__ void mma16816(float c[4],
    uint32_t a0, uint32_t a1, uint32_t a2, uint32_t a3,
    uint32_t b0, uint32_t b1)
{
    asm volatile(
        "mma.sync.aligned.m16n8k16.row.col.f32.bf16.bf16.f32 "
        "{%0,%1,%2,%3}, {%4,%5,%6,%7}, {%8,%9}, {%0,%1,%2,%3};"
        : "+f"(c[0]), "+f"(c[1]), "+f"(c[2]), "+f"(c[3])
        : "r"(a0), "r"(a1), "r"(a2), "r"(a3), "r"(b0), "r"(b1));
}

// ---------------------------------------------------------------------------
// Kernel 1: segment boundaries from sorted owner array.
// ---------------------------------------------------------------------------
__global__ void k_bounds(const int* __restrict__ owner, int N, int G)
{
    int i = blockIdx.x * blockDim.x + threadIdx.x;
    if (i >= N) return;
    int o = owner[i];
    if (i == 0) {
        for (int g = 0; g <= o; ++g) g_segstart[g] = 0;
    } else {
        int po = owner[i - 1];
        for (int g = po + 1; g <= o; ++g) g_segstart[g] = i;
    }
    if (i == N - 1) {
        for (int g = o + 1; g <= G; ++g) g_segstart[g] = N;
    }
}

// ---------------------------------------------------------------------------
// Kernel 2 (FUSED): warp per segment; weights in registers (SHFL broadcast);
// score staging via float4 (1 STS.128 / 1 LDS.128 per atom);
// Phase C: 2 atoms per LDG.128 (R12 loop shape, 7 CTAs/SM).
// ---------------------------------------------------------------------------
__global__ __launch_bounds__(128, 7) void k_fused(
    const float* __restrict__ X,
    const float* __restrict__ w1, const float* __restrict__ b1,
    const float* __restrict__ w2, const float* __restrict__ b2,
    float* __restrict__ out, int N, int G)
{
    __shared__ uint4  sB[4][4][32];          // 8 KB  {bh0,bh1,bl0,bl1}
    __shared__ uint4  sE[4][2][32];          // 4 KB  {b1, w2_0, w2_1, w2_2}
    __shared__ float4 swbuf[4][SEG_CAP];     // 8 KB  packed scores {s0,s1,s2,pad}

    const int lane = threadIdx.x & 31;
    const int wid  = threadIdx.x >> 5;
    const int g    = lane >> 2;   // row group 0..7
    const int tig  = lane & 3;    // thread-in-group
    const int half = lane >> 4;   // 0 or 1 (phase-C row select)
    const int dq   = (lane & 15) * 4;   // phase-C d-column base

    if (wid == 0) {
#pragma unroll
        for (int t = 0; t < 4; ++t) {
            const int col = g + 8 * t;
#pragma unroll
            for (int s = 0; s < 4; ++s) {
                const int p0 = 16 * s + 4 * tig;   // sigma k-permutation
                float w00 = __ldg(&w1[(p0 + 0) * HID_DIM + col]);
                float w01 = __ldg(&w1[(p0 + 1) * HID_DIM + col]);
                float w08 = __ldg(&w1[(p0 + 2) * HID_DIM + col]);
                float w09 = __ldg(&w1[(p0 + 3) * HID_DIM + col]);
                uint4 v;
                v.x = pk2bf(w00, w01);
                v.y = pk2bf(w08, w09);
                v.z = pk2bf(w00 - bfhi(w00), w01 - bfhi(w01));
                v.w = pk2bf(w08 - bfhi(w08), w09 - bfhi(w09));
                sB[t][s][lane] = v;
            }
#pragma unroll
            for (int e = 0; e < 2; ++e) {
                const int col2 = 8 * t + tig * 2 + e;
                uint4 v;
                v.x = __float_as_uint(__ldg(&b1[col2]));
                v.y = __float_as_uint(__ldg(&w2[col2 * H_DIM + 0]));
                v.z = __float_as_uint(__ldg(&w2[col2 * H_DIM + 1]));
                v.w = __float_as_uint(__ldg(&w2[col2 * H_DIM + 2]));
                sE[t][e][lane] = v;
            }
        }
    }
    __syncthreads();

    const float bb0 = __ldg(&b2[0]), bb1 = __ldg(&b2[1]), bb2 = __ldg(&b2[2]);

    float4* swp = swbuf[wid];

    const int warp0 = blockIdx.x * 4 + wid;
    const int nwarp = gridDim.x * 4;

    for (int seg = warp0; seg < G; seg += nwarp) {
        const int s0  = g_segstart[seg];
        const int s1  = g_segstart[seg + 1];
        const int cnt = s1 - s0;
        float* outg = out + (size_t)seg * (D_DIM * H_DIM);

        if (cnt <= 0) {
            if (lane < 16) {
                float4 z = make_float4(0.f, 0.f, 0.f, 0.f);
                float4* o4 = reinterpret_cast<float4*>(outg + lane * 12);
                o4[0] = z; o4[1] = z; o4[2] = z;
            }
            continue;
        }

        // =========== Phase A: scores (mma.sync, k-permuted, trunc split) =====
        const bool fast = (cnt <= SEG_CAP);
        const int ntile = (cnt + 15) >> 4;
        for (int ti = 0; ti < ntile; ++ti) {
            float acc[4][4];
#pragma unroll
            for (int t = 0; t < 4; ++t) {
                acc[t][0] = 0.f; acc[t][1] = 0.f; acc[t][2] = 0.f; acc[t][3] = 0.f;
            }
            const int r0 = s0 + ti * 16 + g;
            const int r1 = r0 + 8;
            const float* x0 = X + (size_t)(r0 < s1 ? r0 : s1 - 1) * D_DIM;
            const float* x1 = X + (size_t)(r1 < s1 ? r1 : s1 - 1) * D_DIM;

#pragma unroll
            for (int s = 0; s < 4; ++s) {
                const int ks = 16 * s + 4 * tig;
                float4 u0 = *reinterpret_cast<const float4*>(x0 + ks);
                float4 u1 = *reinterpret_cast<const float4*>(x1 + ks);

                uint32_t ah0 = pkhi_trunc(u0.x, u0.y);
                uint32_t ah1 = pkhi_trunc(u1.x, u1.y);
                uint32_t ah2 = pkhi_trunc(u0.z, u0.w);
                uint32_t ah3 = pkhi_trunc(u1.z, u1.w);
                uint32_t al0 = pk2bf(u0.x - trunchi(u0.x), u0.y - trunchi(u0.y));
                uint32_t al1 = pk2bf(u1.x - trunchi(u1.x), u1.y - trunchi(u1.y));
                uint32_t al2 = pk2bf(u0.z - trunchi(u0.z), u0.w - trunchi(u0.w));
                uint32_t al3 = pk2bf(u1.z - trunchi(u1.z), u1.w - trunchi(u1.w));

#pragma unroll
                for (int t = 0; t < 4; ++t) {
                    uint4 bf = sB[t][s][lane];
                    mma16816(acc[t], ah0, ah1, ah2, ah3, bf.x, bf.y);
                    mma16816(acc[t], ah0, ah1, ah2, ah3, bf.z, bf.w);
                    mma16816(acc[t], al0, al1, al2, al3, bf.x, bf.y);
                }
            }

#pragma unroll
            for (int row = 0; row < 2; ++row) {
                float q0 = 0.f, q1 = 0.f, q2 = 0.f;
#pragma unroll
                for (int t = 0; t < 4; ++t) {
#pragma unroll
                    for (int e = 0; e < 2; ++e) {
                        uint4 c = sE[t][e][lane];
                        float h = acc[t][row * 2 + e] + __uint_as_float(c.x);
                        float act = __fdividef(h, 1.0f + __expf(-h));
                        q0 = fmaf(act, __uint_as_float(c.y), q0);
                        q1 = fmaf(act, __uint_as_float(c.z), q1);
                        q2 = fmaf(act, __uint_as_float(c.w), q2);
                    }
                }
                q0 += __shfl_xor_sync(0xffffffffu, q0, 1);
                q0 += __shfl_xor_sync(0xffffffffu, q0, 2);
                q1 += __shfl_xor_sync(0xffffffffu, q1, 1);
                q1 += __shfl_xor_sync(0xffffffffu, q1, 2);
                q2 += __shfl_xor_sync(0xffffffffu, q2, 1);
                q2 += __shfl_xor_sync(0xffffffffu, q2, 2);

                const int idx = ti * 16 + g + 8 * row;
                if (tig == 0 && idx < cnt) {
                    if (fast) {
                        swp[idx] = make_float4(q0 + bb0, q1 + bb1, q2 + bb2, 0.f);
                    } else {
                        size_t o = (size_t)(s0 + idx) * H_DIM;
                        g_scores[o + 0] = q0 + bb0;
                        g_scores[o + 1] = q1 + bb1;
                        g_scores[o + 2] = q2 + bb2;
                    }
                }
            }
        }
        __syncwarp();

        // ---- phase-C accumulators: lane owns d = dq..dq+3 for its half-rows
        ull a00 = 0, a01 = 0, a10 = 0, a11 = 0, a20 = 0, a21 = 0;

        // phase C over a chunk of <=128 atoms with weights in exv regs (R12 shape)
        auto phase_c = [&](int gbase, int clen, const float (&exv)[4][3]) {
#pragma unroll
            for (int q = 0; q < 4; ++q) {
                const int blk = 32 * q;
                if (blk >= clen) break;
                const int lim = (clen - blk < 32) ? (clen - blk) : 32;
                const float ws0 = exv[q][0], ws1 = exv[q][1], ws2 = exv[q][2];
                for (int aa = 0; aa < lim; aa += 2) {
                    const int idx = aa + half;
                    const int idc = idx < lim ? idx : lim - 1;
                    float w0 = __shfl_sync(0xffffffffu, ws0, idc);
                    float w1v = __shfl_sync(0xffffffffu, ws1, idc);
                    float w2v = __shfl_sync(0xffffffffu, ws2, idc);
                    if (idx >= lim) { w0 = 0.f; w1v = 0.f; w2v = 0.f; }
                    const float4 xv = *reinterpret_cast<const float4*>(
                        X + (size_t)(gbase + blk + idc) * D_DIM + dq);
                    const ull* xp = reinterpret_cast<const ull*>(&xv);
                    ull p0 = pack2(w0), p1 = pack2(w1v), p2 = pack2(w2v);
                    a00 = fma2(xp[0], p0, a00); a01 = fma2(xp[1], p0, a01);
                    a10 = fma2(xp[0], p1, a10); a11 = fma2(xp[1], p1, a11);
                    a20 = fma2(xp[0], p2, a20); a21 = fma2(xp[1], p2, a21);
                }
            }
        };

        if (fast) {
            // ---- Phase B: scores -> regs (LDS.128), softmax via shuffles ----
            float exv[4][3];
            float m0 = -3.4e38f, m1 = -3.4e38f, m2 = -3.4e38f;
#pragma unroll
            for (int q = 0; q < 4; ++q) {
                int a = lane + 32 * q;
                if (a < cnt) {
                    float4 sc = swp[a];
                    exv[q][0] = sc.x; exv[q][1] = sc.y; exv[q][2] = sc.z;
                    m0 = fmaxf(m0, sc.x);
                    m1 = fmaxf(m1, sc.y);
                    m2 = fmaxf(m2, sc.z);
                } else {
                    exv[q][0] = -3.4e38f; exv[q][1] = -3.4e38f; exv[q][2] = -3.4e38f;
                }
            }
#pragma unroll
            for (int off = 16; off; off >>= 1) {
                m0 = fmaxf(m0, __shfl_xor_sync(0xffffffffu, m0, off));
                m1 = fmaxf(m1, __shfl_xor_sync(0xffffffffu, m1, off));
                m2 = fmaxf(m2, __shfl_xor_sync(0xffffffffu, m2, off));
            }
            float e0 = 0.f, e1 = 0.f, e2 = 0.f;
#pragma unroll
            for (int q = 0; q < 4; ++q) {
                exv[q][0] = __expf(exv[q][0] - m0); e0 += exv[q][0];
                exv[q][1] = __expf(exv[q][1] - m1); e1 += exv[q][1];
                exv[q][2] = __expf(exv[q][2] - m2); e2 += exv[q][2];
            }
#pragma unroll
            for (int off = 16; off; off >>= 1) {
                e0 += __shfl_xor_sync(0xffffffffu, e0, off);
                e1 += __shfl_xor_sync(0xffffffffu, e1, off);
                e2 += __shfl_xor_sync(0xffffffffu, e2, off);
            }
            const float r0v = 1.0f / e0, r1v = 1.0f / e1, r2v = 1.0f / e2;
#pragma unroll
            for (int q = 0; q < 4; ++q) {
                exv[q][0] *= r0v; exv[q][1] *= r1v; exv[q][2] *= r2v;
            }
            phase_c(s0, cnt, exv);
        } else {
            // ---- big segment: m/r over g_scores, then chunked phase C
            float m0 = -3.4e38f, m1 = -3.4e38f, m2 = -3.4e38f;
            for (int n = s0 + lane; n < s1; n += 32) {
                size_t o = (size_t)n * H_DIM;
                m0 = fmaxf(m0, g_scores[o + 0]);
                m1 = fmaxf(m1, g_scores[o + 1]);
                m2 = fmaxf(m2, g_scores[o + 2]);
            }
#pragma unroll
            for (int off = 16; off; off >>= 1) {
                m0 = fmaxf(m0, __shfl_xor_sync(0xffffffffu, m0, off));
                m1 = fmaxf(m1, __shfl_xor_sync(0xffffffffu, m1, off));
                m2 = fmaxf(m2, __shfl_xor_sync(0xffffffffu, m2, off));
            }
            float e0 = 0.f, e1 = 0.f, e2 = 0.f;
            for (int n = s0 + lane; n < s1; n += 32) {
                size_t o = (size_t)n * H_DIM;
                e0 += __expf(g_scores[o + 0] - m0);
                e1 += __expf(g_scores[o + 1] - m1);
                e2 += __expf(g_scores[o + 2] - m2);
            }
#pragma unroll
            for (int off = 16; off; off >>= 1) {
                e0 += __shfl_xor_sync(0xffffffffu, e0, off);
                e1 += __shfl_xor_sync(0xffffffffu, e1, off);
                e2 += __shfl_xor_sync(0xffffffffu, e2, off);
            }
            const float r0v = 1.0f / e0, r1v = 1.0f / e1, r2v = 1.0f / e2;

            for (int cb = 0; cb < cnt; cb += SEG_CAP) {
                const int clen = min(SEG_CAP, cnt - cb);
                float exv[4][3];
#pragma unroll
                for (int q = 0; q < 4; ++q) {
                    int a = lane + 32 * q;
                    if (a < clen) {
                        size_t o = (size_t)(s0 + cb + a) * H_DIM;
                        exv[q][0] = __expf(g_scores[o + 0] - m0) * r0v;
                        exv[q][1] = __expf(g_scores[o + 1] - m1) * r1v;
                        exv[q][2] = __expf(g_scores[o + 2] - m2) * r2v;
                    } else {
                        exv[q][0] = 0.f; exv[q][1] = 0.f; exv[q][2] = 0.f;
                    }
                }
                phase_c(s0 + cb, clen, exv);
            }
        }

        // ---- merge half-warps and write out: lane<16 owns d = lane*4..+3 ----
        float v[12];
        unpack2(a00, v[0], v[3]);   // d0h0, d1h0
        unpack2(a10, v[1], v[4]);   // d0h1, d1h1
        unpack2(a20, v[2], v[5]);   // d0h2, d1h2
        unpack2(a01, v[6], v[9]);   // d2h0, d3h0
        unpack2(a11, v[7], v[10]);  // d2h1, d3h1
        unpack2(a21, v[8], v[11]);  // d2h2, d3h2
#pragma unroll
        for (int i = 0; i < 12; ++i)
            v[i] += __shfl_xor_sync(0xffffffffu, v[i], 16);
        if (lane < 16) {
            float4* o4 = reinterpret_cast<float4*>(outg + lane * 12);
            o4[0] = make_float4(v[0], v[1], v[2],  v[3]);
            o4[1] = make_float4(v[4], v[5], v[6],  v[7]);
            o4[2] = make_float4(v[8], v[9], v[10], v[11]);
        }
    }
}

// ---------------------------------------------------------------------------
extern "C" void kernel_launch(void* const* d_in, const int* in_sizes, int n_in,
                              void* d_out, int out_size)
{
    const float* X     = (const float*)d_in[0];
    const float* w1    = (const float*)d_in[1];
    const float* b1    = (const float*)d_in[2];
    const float* w2    = (const float*)d_in[3];
    const float* b2    = (const float*)d_in[4];
    const int*   owner = (const int*)  d_in[5];

    const int N = in_sizes[5];
    const int G = out_size / (D_DIM * H_DIM);

    k_bounds<<<(N + 255) / 256, 256>>>(owner, N, G);
    k_fused<<<1036, 128>>>(X, w1, b1, w2, b2, (float*)d_out, N, G);
}

// round 15
// speedup vs baseline: 1.3782x; 1.0938x over previous
#include <cuda_runtime.h>
#include <cuda_bf16.h>
#include <cstdint>

// Problem shape (fixed by dataset): N=2,000,000 atoms, D=64, HID=32, H=3, G=50,000
#define D_DIM   64
#define HID_DIM 32
#define H_DIM   3

#define MAX_N 2000000
#define MAX_G 50000
#define SEG_CAP 128

typedef unsigned long long ull;

// Scratch (device globals)
__device__ float g_scores[(size_t)MAX_N * H_DIM];   // big-segment fallback only
__device__ int   g_segstart[MAX_G + 1];

// ---------------- packed fp32x2 helpers ----------------
__device__ __forceinline__ ull pack2(float v) {
    ull r; asm("mov.b64 %0, {%1, %1};" : "=l"(r) : "f"(v)); return r;
}
__device__ __forceinline__ ull fma2(ull a, ull b, ull c) {
    ull d; asm("fma.rn.f32x2 %0, %1, %2, %3;" : "=l"(d) : "l"(a), "l"(b), "l"(c)); return d;
}
__device__ __forceinline__ void unpack2(ull v, float& lo, float& hi) {
    asm("mov.b64 {%0, %1}, %2;" : "=f"(lo), "=f"(hi) : "l"(v));
}

// ---------------- bf16 helpers ----------------
__device__ __forceinline__ uint32_t pk2bf(float a, float b) {
    __nv_bfloat162 h = __floats2bfloat162_rn(a, b);
    return *reinterpret_cast<uint32_t*>(&h);
}
__device__ __forceinline__ float bfhi(float x) {
    return __bfloat162float(__float2bfloat16_rn(x));
}
// hi-part via truncation: one PRMT packs the top 16 bits of (a,b) -> bf16x2
__device__ __forceinline__ uint32_t pkhi_trunc(float a, float b) {
    uint32_t r;
    asm("prmt.b32 %0, %1, %2, 0x7632;"
        : "=r"(r) : "r"(__float_as_uint(a)), "r"(__float_as_uint(b)));
    return r;
}
__device__ __forceinline__ float trunchi(float x) {
    return __uint_as_float(__float_as_uint(x) & 0xffff0000u);
}

// warp-level tensor-core MMA (sm_80+ feature set; compiles for plain sm_103)
__device__ __forceinline__ void mma16816(float c[4],
    uint32_t a0, uint32_t a1, uint32_t a2, uint32_t a3,
    uint32_t b0, uint32_t b1)
{
    asm volatile(
        "mma.sync.aligned.m16n8k16.row.col.f32.bf16.bf16.f32 "
        "{%0,%1,%2,%3}, {%4,%5,%6,%7}, {%8,%9}, {%0,%1,%2,%3};"
        : "+f"(c[0]), "+f"(c[1]), "+f"(c[2]), "+f"(c[3])
        : "r"(a0), "r"(a1), "r"(a2), "r"(a3), "r"(b0), "r"(b1));
}

// ---------------------------------------------------------------------------
// Kernel 1: segment boundaries from sorted owner array.
// ---------------------------------------------------------------------------
__global__ void k_bounds(const int* __restrict__ owner, int N, int G)
{
    int i = blockIdx.x * blockDim.x + threadIdx.x;
    if (i >= N) return;
    int o = owner[i];
    if (i == 0) {
        for (int g = 0; g <= o; ++g) g_segstart[g] = 0;
    } else {
        int po = owner[i - 1];
        for (int g = po + 1; g <= o; ++g) g_segstart[g] = i;
    }
    if (i == N - 1) {
        for (int g = o + 1; g <= G; ++g) g_segstart[g] = N;
    }
}

// ---------------------------------------------------------------------------
// Kernel 2 (FUSED): warp per contiguous segment run; Phase-A tiles aligned to
// absolute 16-atom boundaries, cached in a 128-slot smem ring (atom & 127) so
// adjacent segments share boundary tiles (computed once). Weights broadcast
// by SHFL; Phase C: 2 atoms per LDG.128 (R12 loop shape, 7 CTAs/SM).
// ---------------------------------------------------------------------------
__global__ __launch_bounds__(128, 7) void k_fused(
    const float* __restrict__ X,
    const float* __restrict__ w1, const float* __restrict__ b1,
    const float* __restrict__ w2, const float* __restrict__ b2,
    float* __restrict__ out, int N, int G)
{
    __shared__ uint4  sB[4][4][32];       // 8 KB  {bh0,bh1,bl0,bl1}
    __shared__ uint4  sE[4][2][32];       // 4 KB  {b1, w2_0, w2_1, w2_2}
    __shared__ float4 swbuf[4][128];      // 8 KB  score ring, slot = atom & 127

    const int lane = threadIdx.x & 31;
    const int wid  = threadIdx.x >> 5;
    const int g    = lane >> 2;   // row group 0..7
    const int tig  = lane & 3;    // thread-in-group
    const int half = lane >> 4;   // 0 or 1 (phase-C row select)
    const int dq   = (lane & 15) * 4;   // phase-C d-column base

    if (wid == 0) {
#pragma unroll
        for (int t = 0; t < 4; ++t) {
            const int col = g + 8 * t;
#pragma unroll
            for (int s = 0; s < 4; ++s) {
                const int p0 = 16 * s + 4 * tig;   // sigma k-permutation
                float w00 = __ldg(&w1[(p0 + 0) * HID_DIM + col]);
                float w01 = __ldg(&w1[(p0 + 1) * HID_DIM + col]);
                float w08 = __ldg(&w1[(p0 + 2) * HID_DIM + col]);
                float w09 = __ldg(&w1[(p0 + 3) * HID_DIM + col]);
                uint4 v;
                v.x = pk2bf(w00, w01);
                v.y = pk2bf(w08, w09);
                v.z = pk2bf(w00 - bfhi(w00), w01 - bfhi(w01));
                v.w = pk2bf(w08 - bfhi(w08), w09 - bfhi(w09));
                sB[t][s][lane] = v;
            }
#pragma unroll
            for (int e = 0; e < 2; ++e) {
                const int col2 = 8 * t + tig * 2 + e;
                uint4 v;
                v.x = __float_as_uint(__ldg(&b1[col2]));
                v.y = __float_as_uint(__ldg(&w2[col2 * H_DIM + 0]));
                v.z = __float_as_uint(__ldg(&w2[col2 * H_DIM + 1]));
                v.w = __float_as_uint(__ldg(&w2[col2 * H_DIM + 2]));
                sE[t][e][lane] = v;
            }
        }
    }
    __syncthreads();

    const float bb0 = __ldg(&b2[0]), bb1 = __ldg(&b2[1]), bb2 = __ldg(&b2[2]);

    float4* swp = swbuf[wid];

    const int wg    = blockIdx.x * 4 + wid;
    const int nwarp = gridDim.x * 4;
    const int seglo = (int)((long long)wg * G / nwarp);
    const int seghi = (int)((long long)(wg + 1) * G / nwarp);

    int prev_tile = -1;   // last atom-tile whose scores sit in the ring

    // ---- one 16-atom tile (absolute tile index t) -> scores into ring ----
    auto do_tile_ring = [&](int t) {
        float acc[4][4];
#pragma unroll
        for (int u = 0; u < 4; ++u) {
            acc[u][0] = 0.f; acc[u][1] = 0.f; acc[u][2] = 0.f; acc[u][3] = 0.f;
        }
        const int r0 = (t << 4) + g;
        const int r1 = r0 + 8;
        const float* x0 = X + (size_t)(r0 < N ? r0 : N - 1) * D_DIM;
        const float* x1 = X + (size_t)(r1 < N ? r1 : N - 1) * D_DIM;

#pragma unroll
        for (int s = 0; s < 4; ++s) {
            const int ks = 16 * s + 4 * tig;
            float4 u0 = *reinterpret_cast<const float4*>(x0 + ks);
            float4 u1 = *reinterpret_cast<const float4*>(x1 + ks);

            uint32_t ah0 = pkhi_trunc(u0.x, u0.y);
            uint32_t ah1 = pkhi_trunc(u1.x, u1.y);
            uint32_t ah2 = pkhi_trunc(u0.z, u0.w);
            uint32_t ah3 = pkhi_trunc(u1.z, u1.w);
            uint32_t al0 = pk2bf(u0.x - trunchi(u0.x), u0.y - trunchi(u0.y));
            uint32_t al1 = pk2bf(u1.x - trunchi(u1.x), u1.y - trunchi(u1.y));
            uint32_t al2 = pk2bf(u0.z - trunchi(u0.z), u0.w - trunchi(u0.w));
            uint32_t al3 = pk2bf(u1.z - trunchi(u1.z), u1.w - trunchi(u1.w));

#pragma unroll
            for (int u = 0; u < 4; ++u) {
                uint4 bf = sB[u][s][lane];
                mma16816(acc[u], ah0, ah1, ah2, ah3, bf.x, bf.y);
                mma16816(acc[u], ah0, ah1, ah2, ah3, bf.z, bf.w);
                mma16816(acc[u], al0, al1, al2, al3, bf.x, bf.y);
            }
        }

#pragma unroll
        for (int row = 0; row < 2; ++row) {
            float q0 = 0.f, q1 = 0.f, q2 = 0.f;
#pragma unroll
            for (int u = 0; u < 4; ++u) {
#pragma unroll
                for (int e = 0; e < 2; ++e) {
                    uint4 c = sE[u][e][lane];
                    float h = acc[u][row * 2 + e] + __uint_as_float(c.x);
                    float act = __fdividef(h, 1.0f + __expf(-h));
                    q0 = fmaf(act, __uint_as_float(c.y), q0);
                    q1 = fmaf(act, __uint_as_float(c.z), q1);
                    q2 = fmaf(act, __uint_as_float(c.w), q2);
                }
            }
            q0 += __shfl_xor_sync(0xffffffffu, q0, 1);
            q0 += __shfl_xor_sync(0xffffffffu, q0, 2);
            q1 += __shfl_xor_sync(0xffffffffu, q1, 1);
            q1 += __shfl_xor_sync(0xffffffffu, q1, 2);
            q2 += __shfl_xor_sync(0xffffffffu, q2, 1);
            q2 += __shfl_xor_sync(0xffffffffu, q2, 2);

            const int atom = (t << 4) + g + 8 * row;
            if (tig == 0 && atom < N)
                swp[atom & 127] = make_float4(q0 + bb0, q1 + bb1, q2 + bb2, 0.f);
        }
    };

    // ---- phase C over a chunk of <=128 atoms with weights in exv regs ----
    ull a00, a01, a10, a11, a20, a21;
    auto phase_c = [&](int gbase, int clen, const float (&exv)[4][3]) {
#pragma unroll
        for (int q = 0; q < 4; ++q) {
            const int blk = 32 * q;
            if (blk >= clen) break;
            const int lim = (clen - blk < 32) ? (clen - blk) : 32;
            const float ws0 = exv[q][0], ws1 = exv[q][1], ws2 = exv[q][2];
            for (int aa = 0; aa < lim; aa += 2) {
                const int idx = aa + half;
                const int idc = idx < lim ? idx : lim - 1;
                float w0 = __shfl_sync(0xffffffffu, ws0, idc);
                float w1v = __shfl_sync(0xffffffffu, ws1, idc);
                float w2v = __shfl_sync(0xffffffffu, ws2, idc);
                if (idx >= lim) { w0 = 0.f; w1v = 0.f; w2v = 0.f; }
                const float4 xv = *reinterpret_cast<const float4*>(
                    X + (size_t)(gbase + blk + idc) * D_DIM + dq);
                const ull* xp = reinterpret_cast<const ull*>(&xv);
                ull p0 = pack2(w0), p1 = pack2(w1v), p2 = pack2(w2v);
                a00 = fma2(xp[0], p0, a00); a01 = fma2(xp[1], p0, a01);
                a10 = fma2(xp[0], p1, a10); a11 = fma2(xp[1], p1, a11);
                a20 = fma2(xp[0], p2, a20); a21 = fma2(xp[1], p2, a21);
            }
        }
    };

    for (int seg = seglo; seg < seghi; ++seg) {
        const int s0  = g_segstart[seg];
        const int s1  = g_segstart[seg + 1];
        const int cnt = s1 - s0;
        float* outg = out + (size_t)seg * (D_DIM * H_DIM);

        if (cnt <= 0) {           // ring untouched; keep prev_tile
            if (lane < 16) {
                float4 z = make_float4(0.f, 0.f, 0.f, 0.f);
                float4* o4 = reinterpret_cast<float4*>(outg + lane * 12);
                o4[0] = z; o4[1] = z; o4[2] = z;
            }
            continue;
        }

        const int t0 = s0 >> 4;
        const int t1 = (s1 - 1) >> 4;
        const bool fast = (s1 - (t0 << 4)) <= 128;   // span fits the ring

        a00 = 0; a01 = 0; a10 = 0; a11 = 0; a20 = 0; a21 = 0;

        if (fast) {
            // ===== Phase A: only tiles not already in the ring =====
            const int tstart = (t0 == prev_tile) ? t0 + 1 : t0;
            for (int t = tstart; t <= t1; ++t) do_tile_ring(t);
            prev_tile = t1;
            __syncwarp();

            // ===== Phase B: scores from ring -> regs, softmax via shuffles ====
            float exv[4][3];
            float m0 = -3.4e38f, m1 = -3.4e38f, m2 = -3.4e38f;
#pragma unroll
            for (int q = 0; q < 4; ++q) {
                int a = lane + 32 * q;
                if (a < cnt) {
                    float4 sc = swp[(s0 + a) & 127];
                    exv[q][0] = sc.x; exv[q][1] = sc.y; exv[q][2] = sc.z;
                    m0 = fmaxf(m0, sc.x);
                    m1 = fmaxf(m1, sc.y);
                    m2 = fmaxf(m2, sc.z);
                } else {
                    exv[q][0] = -3.4e38f; exv[q][1] = -3.4e38f; exv[q][2] = -3.4e38f;
                }
            }
#pragma unroll
            for (int off = 16; off; off >>= 1) {
                m0 = fmaxf(m0, __shfl_xor_sync(0xffffffffu, m0, off));
                m1 = fmaxf(m1, __shfl_xor_sync(0xffffffffu, m1, off));
                m2 = fmaxf(m2, __shfl_xor_sync(0xffffffffu, m2, off));
            }
            float e0 = 0.f, e1 = 0.f, e2 = 0.f;
#pragma unroll
            for (int q = 0; q < 4; ++q) {
                exv[q][0] = __expf(exv[q][0] - m0); e0 += exv[q][0];
                exv[q][1] = __expf(exv[q][1] - m1); e1 += exv[q][1];
                exv[q][2] = __expf(exv[q][2] - m2); e2 += exv[q][2];
            }
#pragma unroll
            for (int off = 16; off; off >>= 1) {
                e0 += __shfl_xor_sync(0xffffffffu, e0, off);
                e1 += __shfl_xor_sync(0xffffffffu, e1, off);
                e2 += __shfl_xor_sync(0xffffffffu, e2, off);
            }
            const float r0v = 1.0f / e0, r1v = 1.0f / e1, r2v = 1.0f / e2;
#pragma unroll
            for (int q = 0; q < 4; ++q) {
                exv[q][0] *= r0v; exv[q][1] *= r1v; exv[q][2] *= r2v;
            }
            __syncwarp();   // ring reads done before next segment overwrites
            phase_c(s0, cnt, exv);
        } else {
            // ===== rare big-segment path via g_scores (old-style tiles) =====
            const int ntile = (cnt + 15) >> 4;
            for (int ti = 0; ti < ntile; ++ti) {
                float acc[4][4];
#pragma unroll
                for (int u = 0; u < 4; ++u) {
                    acc[u][0] = 0.f; acc[u][1] = 0.f; acc[u][2] = 0.f; acc[u][3] = 0.f;
                }
                const int r0 = s0 + ti * 16 + g;
                const int r1 = r0 + 8;
                const float* x0 = X + (size_t)(r0 < s1 ? r0 : s1 - 1) * D_DIM;
                const float* x1 = X + (size_t)(r1 < s1 ? r1 : s1 - 1) * D_DIM;

#pragma unroll
                for (int s = 0; s < 4; ++s) {
                    const int ks = 16 * s + 4 * tig;
                    float4 u0 = *reinterpret_cast<const float4*>(x0 + ks);
                    float4 u1 = *reinterpret_cast<const float4*>(x1 + ks);
                    uint32_t ah0 = pkhi_trunc(u0.x, u0.y);
                    uint32_t ah1 = pkhi_trunc(u1.x, u1.y);
                    uint32_t ah2 = pkhi_trunc(u0.z, u0.w);
                    uint32_t ah3 = pkhi_trunc(u1.z, u1.w);
                    uint32_t al0 = pk2bf(u0.x - trunchi(u0.x), u0.y - trunchi(u0.y));
                    uint32_t al1 = pk2bf(u1.x - trunchi(u1.x), u1.y - trunchi(u1.y));
                    uint32_t al2 = pk2bf(u0.z - trunchi(u0.z), u0.w - trunchi(u0.w));
                    uint32_t al3 = pk2bf(u1.z - trunchi(u1.z), u1.w - trunchi(u1.w));
#pragma unroll
                    for (int u = 0; u < 4; ++u) {
                        uint4 bf = sB[u][s][lane];
                        mma16816(acc[u], ah0, ah1, ah2, ah3, bf.x, bf.y);
                        mma16816(acc[u], ah0, ah1, ah2, ah3, bf.z, bf.w);
                        mma16816(acc[u], al0, al1, al2, al3, bf.x, bf.y);
                    }
                }
#pragma unroll
                for (int row = 0; row < 2; ++row) {
                    float q0 = 0.f, q1 = 0.f, q2 = 0.f;
#pragma unroll
                    for (int u = 0; u < 4; ++u) {
#pragma unroll
                        for (int e = 0; e < 2; ++e) {
                            uint4 c = sE[u][e][lane];
                            float h = acc[u][row * 2 + e] + __uint_as_float(c.x);
                            float act = __fdividef(h, 1.0f + __expf(-h));
                            q0 = fmaf(act, __uint_as_float(c.y), q0);
                            q1 = fmaf(act, __uint_as_float(c.z), q1);
                            q2 = fmaf(act, __uint_as_float(c.w), q2);
                        }
                    }
                    q0 += __shfl_xor_sync(0xffffffffu, q0, 1);
                    q0 += __shfl_xor_sync(0xffffffffu, q0, 2);
                    q1 += __shfl_xor_sync(0xffffffffu, q1, 1);
                    q1 += __shfl_xor_sync(0xffffffffu, q1, 2);
                    q2 += __shfl_xor_sync(0xffffffffu, q2, 1);
                    q2 += __shfl_xor_sync(0xffffffffu, q2, 2);
                    const int idx = ti * 16 + g + 8 * row;
                    if (tig == 0 && idx < cnt) {
                        size_t o = (size_t)(s0 + idx) * H_DIM;
                        g_scores[o + 0] = q0 + bb0;
                        g_scores[o + 1] = q1 + bb1;
                        g_scores[o + 2] = q2 + bb2;
                    }
                }
            }
            __syncwarp();
            prev_tile = -1;

            float m0 = -3.4e38f, m1 = -3.4e38f, m2 = -3.4e38f;
            for (int n = s0 + lane; n < s1; n += 32) {
                size_t o = (size_t)n * H_DIM;
                m0 = fmaxf(m0, g_scores[o + 0]);
                m1 = fmaxf(m1, g_scores[o + 1]);
                m2 = fmaxf(m2, g_scores[o + 2]);
            }
#pragma unroll
            for (int off = 16; off; off >>= 1) {
                m0 = fmaxf(m0, __shfl_xor_sync(0xffffffffu, m0, off));
                m1 = fmaxf(m1, __shfl_xor_sync(0xffffffffu, m1, off));
                m2 = fmaxf(m2, __shfl_xor_sync(0xffffffffu, m2, off));
            }
            float e0 = 0.f, e1 = 0.f, e2 = 0.f;
            for (int n = s0 + lane; n < s1; n += 32) {
                size_t o = (size_t)n * H_DIM;
                e0 += __expf(g_scores[o + 0] - m0);
                e1 += __expf(g_scores[o + 1] - m1);
                e2 += __expf(g_scores[o + 2] - m2);
            }
#pragma unroll
            for (int off = 16; off; off >>= 1) {
                e0 += __shfl_xor_sync(0xffffffffu, e0, off);
                e1 += __shfl_xor_sync(0xffffffffu, e1, off);
                e2 += __shfl_xor_sync(0xffffffffu, e2, off);
            }
            const float r0v = 1.0f / e0, r1v = 1.0f / e1, r2v = 1.0f / e2;

            for (int cb = 0; cb < cnt; cb += SEG_CAP) {
                const int clen = min(SEG_CAP, cnt - cb);
                float exv[4][3];
#pragma unroll
                for (int q = 0; q < 4; ++q) {
                    int a = lane + 32 * q;
                    if (a < clen) {
                        size_t o = (size_t)(s0 + cb + a) * H_DIM;
                        exv[q][0] = __expf(g_scores[o + 0] - m0) * r0v;
                        exv[q][1] = __expf(g_scores[o + 1] - m1) * r1v;
                        exv[q][2] = __expf(g_scores[o + 2] - m2) * r2v;
                    } else {
                        exv[q][0] = 0.f; exv[q][1] = 0.f; exv[q][2] = 0.f;
                    }
                }
                phase_c(s0 + cb, clen, exv);
            }
        }

        // ---- merge half-warps and write out: lane<16 owns d = lane*4..+3 ----
        float v[12];
        unpack2(a00, v[0], v[3]);   // d0h0, d1h0
        unpack2(a10, v[1], v[4]);   // d0h1, d1h1
        unpack2(a20, v[2], v[5]);   // d0h2, d1h2
        unpack2(a01, v[6], v[9]);   // d2h0, d3h0
        unpack2(a11, v[7], v[10]);  // d2h1, d3h1
        unpack2(a21, v[8], v[11]);  // d2h2, d3h2
#pragma unroll
        for (int i = 0; i < 12; ++i)
            v[i] += __shfl_xor_sync(0xffffffffu, v[i], 16);
        if (lane < 16) {
            float4* o4 = reinterpret_cast<float4*>(outg + lane * 12);
            o4[0] = make_float4(v[0], v[1], v[2],  v[3]);
            o4[1] = make_float4(v[4], v[5], v[6],  v[7]);
            o4[2] = make_float4(v[8], v[9], v[10], v[11]);
        }
    }
}

// ---------------------------------------------------------------------------
extern "C" void kernel_launch(void* const* d_in, const int* in_sizes, int n_in,
                              void* d_out, int out_size)
{
    const float* X     = (const float*)d_in[0];
    const float* w1    = (const float*)d_in[1];
    const float* b1    = (const float*)d_in[2];
    const float* w2    = (const float*)d_in[3];
    const float* b2    = (const float*)d_in[4];
    const int*   owner = (const int*)  d_in[5];

    const int N = in_sizes[5];
    const int G = out_size / (D_DIM * H_DIM);

    k_bounds<<<(N + 255) / 256, 256>>>(owner, N, G);
    k_fused<<<1036, 128>>>(X, w1, b1, w2, b2, (float*)d_out, N, G);
}